// round 10
// baseline (speedup 1.0000x reference)
#include <cuda_runtime.h>
#include <cuda_fp16.h>
#include <math.h>
#include <stdint.h>

// Problem constants
#define DIMK 4096
#define HQ   32
#define HKV  8
#define HD   128
#define REP  (HQ / HKV)
#define SMAX 2048
#define ATT_SCALE 0.08838834764831845f   // 1/sqrt(128)
#define W_SCALE   1024.0f
#define W_UNSCALE 0.0009765625f          // 2^-10

// ---------------------------------------------------------------------------
// Scratch (device globals: allocation-free per harness rules)
// ---------------------------------------------------------------------------
__device__ float g_Q[(size_t)SMAX * HQ * HD];    // fp32 Q before rope/cast
__device__ float g_K[(size_t)SMAX * HKV * HD];   // fp32 K before rope/cast

__device__ __half g_xh[(size_t)SMAX * DIMK];
__device__ __half g_oh[(size_t)SMAX * DIMK];     // attention output (fp16)
__device__ __half g_qh[(size_t)SMAX * HQ * HD];  // fp16 Q after rope
__device__ __half g_kh[(size_t)SMAX * HKV * HD]; // fp16 K after rope
__device__ __half g_vh[(size_t)SMAX * HKV * HD]; // fp16 V
__device__ __half g_wqh[(size_t)4096 * 4096];    // scaled x1024, hi
__device__ __half g_wql[(size_t)4096 * 4096];    // scaled x1024, lo
__device__ __half g_wkh[(size_t)1024 * 4096];
__device__ __half g_wkl[(size_t)1024 * 4096];
__device__ __half g_wvh[(size_t)1024 * 4096];    // plain fp16 (single-pass)
__device__ __half g_woh[(size_t)4096 * 4096];    // plain fp16 (single-pass)

// ---------------------------------------------------------------------------
// Helpers
// ---------------------------------------------------------------------------
static __device__ __forceinline__ uint32_t smem_u32(const void* p) {
    uint32_t a;
    asm("{ .reg .u64 t; cvta.to.shared.u64 t, %1; cvt.u32.u64 %0, t; }"
        : "=r"(a) : "l"(p));
    return a;
}

static __device__ __forceinline__ void ldsm4(uint32_t& r0, uint32_t& r1,
                                             uint32_t& r2, uint32_t& r3,
                                             uint32_t addr) {
    asm volatile("ldmatrix.sync.aligned.m8n8.x4.shared.b16 {%0,%1,%2,%3}, [%4];"
                 : "=r"(r0), "=r"(r1), "=r"(r2), "=r"(r3) : "r"(addr));
}

static __device__ __forceinline__ void ldsm4t(uint32_t& r0, uint32_t& r1,
                                              uint32_t& r2, uint32_t& r3,
                                              uint32_t addr) {
    asm volatile("ldmatrix.sync.aligned.m8n8.x4.trans.shared.b16 {%0,%1,%2,%3}, [%4];"
                 : "=r"(r0), "=r"(r1), "=r"(r2), "=r"(r3) : "r"(addr));
}

static __device__ __forceinline__ void mma16816(float* c, uint32_t a0, uint32_t a1,
                                                uint32_t a2, uint32_t a3,
                                                uint32_t b0, uint32_t b1) {
    asm volatile(
        "mma.sync.aligned.m16n8k16.row.col.f32.f16.f16.f32 "
        "{%0,%1,%2,%3}, {%4,%5,%6,%7}, {%8,%9}, {%0,%1,%2,%3};"
        : "+f"(c[0]), "+f"(c[1]), "+f"(c[2]), "+f"(c[3])
        : "r"(a0), "r"(a1), "r"(a2), "r"(a3), "r"(b0), "r"(b1));
}

static __device__ __forceinline__ uint32_t pack_h2(float a, float b) {
    __half2 h = __floats2half2_rn(a, b);
    return *(uint32_t*)&h;
}

// ---------------------------------------------------------------------------
// Cast fp32 -> fp16.  n % 4 == 0.
// ---------------------------------------------------------------------------
__global__ void cast_kernel(const float* __restrict__ X,
                            __half* __restrict__ H, int n4) {
    int i = blockIdx.x * blockDim.x + threadIdx.x;
    if (i >= n4) return;
    float4 v = ((const float4*)X)[i];
    __half2* Hp = (__half2*)H;
    Hp[2 * i]     = __floats2half2_rn(v.x, v.y);
    Hp[2 * i + 1] = __floats2half2_rn(v.z, v.w);
}

// ---------------------------------------------------------------------------
// Split fp32 weight -> (fp16 hi, fp16 lo), pre-scaled by 1024 (subnormal guard)
// ---------------------------------------------------------------------------
__global__ void split_w_kernel(const float* __restrict__ X,
                               __half* __restrict__ H,
                               __half* __restrict__ L, int n4) {
    int i = blockIdx.x * blockDim.x + threadIdx.x;
    if (i >= n4) return;
    float4 v = ((const float4*)X)[i];
    float sx = v.x * W_SCALE, sy = v.y * W_SCALE;
    float sz = v.z * W_SCALE, sw = v.w * W_SCALE;
    __half hx = __float2half_rn(sx);
    __half hy = __float2half_rn(sy);
    __half hz = __float2half_rn(sz);
    __half hw = __float2half_rn(sw);
    __half lx = __float2half_rn(sx - __half2float(hx));
    __half ly = __float2half_rn(sy - __half2float(hy));
    __half lz = __float2half_rn(sz - __half2float(hz));
    __half lw = __float2half_rn(sw - __half2float(hw));
    __half2* Hp = (__half2*)H;
    __half2* Lp = (__half2*)L;
    Hp[2 * i]     = __half2(hx, hy);
    Hp[2 * i + 1] = __half2(hz, hw);
    Lp[2 * i]     = __half2(lx, ly);
    Lp[2 * i + 1] = __half2(lz, lw);
}

// ---------------------------------------------------------------------------
// RoPE + cast: read fp32 T[S,nh,128], write fp16 rotated.
// ---------------------------------------------------------------------------
__global__ void rope_cast_kernel(const float* __restrict__ T,
                                 const float* __restrict__ fc,
                                 __half* __restrict__ O, int S, int nh) {
    int idx   = blockIdx.x * blockDim.x + threadIdx.x;
    int total = S * nh * (HD / 2);
    if (idx >= total) return;
    int i = idx & 63;
    int h = (idx >> 6) % nh;
    int s = idx / (64 * nh);
    float c  = fc[(size_t)s * HD + 2 * i];
    float sn = fc[(size_t)s * HD + 2 * i + 1];
    size_t base = ((size_t)s * nh + h) * HD + 2 * i;
    float t0 = T[base];
    float t1 = T[base + 1];
    *(__half2*)(O + base) = __floats2half2_rn(t0 * c - t1 * sn, t0 * sn + t1 * c);
}

// ---------------------------------------------------------------------------
// Shared GEMM geometry: 128x128 CTA tile, BK=32, 8 warps (2x4), warp 64x32.
// ---------------------------------------------------------------------------
#define GSTAGES 3
#define GBK     32
#define RS_B    80
#define GTILE_B (128 * RS_B)
#define GSTAGE3_B (3 * GTILE_B)
#define GSMEM3_BYTES (GSTAGES * GSTAGE3_B)
#define GSTAGE2_B (2 * GTILE_B)
#define GSMEM2_BYTES (GSTAGES * GSTAGE2_B)

static __device__ __forceinline__ void tile_cp(uint32_t sbase,
        const __half* __restrict__ src, int r0, int kc, int K, int tid) {
#pragma unroll
    for (int i = 0; i < 2; i++) {
        int ch  = tid + i * 256;
        int r   = ch >> 2;
        int c16 = ch & 3;
        uint32_t dst = sbase + (uint32_t)(r * RS_B + c16 * 16);
        const void* g = src + (size_t)(r0 + r) * K + kc + c16 * 8;
        asm volatile("cp.async.cg.shared.global [%0], [%1], 16;"
                     :: "r"(dst), "l"(g) : "memory");
    }
}

// ---------------------------------------------------------------------------
// 2-pass GEMM: C = (1/1024) * A @ (Bh+Bl)^T
// ---------------------------------------------------------------------------
__global__ __launch_bounds__(256, 2)
void gemm_f16x2(const __half* __restrict__ A, const __half* __restrict__ Bh,
                const __half* __restrict__ Bl,
                float* __restrict__ C, int M, int N, int K) {
    extern __shared__ __align__(16) char smraw[];
    const uint32_t sb  = smem_u32(smraw);
    const int tid  = threadIdx.x;
    const int wid  = tid >> 5;
    const int lane = tid & 31;
    const int wm   = wid >> 2;
    const int wn   = wid & 3;
    const int bm = blockIdx.y * 128;
    const int bn = blockIdx.x * 128;

    const int a_row = wm * 64 + (lane & 15);
    const int a_colB = ((lane >> 4) * 8) * 2;
    const int b_row = wn * 32 + (lane & 7) + ((lane >> 4) * 8);
    const int b_colB = (((lane >> 3) & 1) * 8) * 2;
    const uint32_t a_off = (uint32_t)(a_row * RS_B + a_colB);
    const uint32_t b_off = (uint32_t)(b_row * RS_B + b_colB);

    float acc[4][4][4];
#pragma unroll
    for (int i = 0; i < 4; i++)
#pragma unroll
        for (int j = 0; j < 4; j++)
#pragma unroll
            for (int k = 0; k < 4; k++) acc[i][j][k] = 0.f;

    const int NC = K / GBK;

#pragma unroll
    for (int i = 0; i < GSTAGES; i++) {
        const uint32_t stg = sb + i * GSTAGE3_B;
        tile_cp(stg,               A,  bm, i * GBK, K, tid);
        tile_cp(stg + GTILE_B,     Bh, bn, i * GBK, K, tid);
        tile_cp(stg + 2 * GTILE_B, Bl, bn, i * GBK, K, tid);
        asm volatile("cp.async.commit_group;" ::: "memory");
    }

    int s = 0;
    for (int c = 0; c < NC; c++) {
        asm volatile("cp.async.wait_group %0;" :: "n"(GSTAGES - 1) : "memory");
        __syncthreads();

        const uint32_t stg = sb + s * GSTAGE3_B;
#pragma unroll
        for (int k16 = 0; k16 < 2; k16++) {
            const uint32_t kB = (uint32_t)(k16 * 16 * 2);
            uint32_t a[4][4];
#pragma unroll
            for (int mb = 0; mb < 4; mb++)
                ldsm4(a[mb][0], a[mb][1], a[mb][2], a[mb][3],
                      stg + a_off + mb * (16 * RS_B) + kB);
#pragma unroll
            for (int p = 0; p < 2; p++) {
                const uint32_t Bt = stg + (1 + p) * GTILE_B;
                uint32_t b[8];
                ldsm4(b[0], b[1], b[2], b[3], Bt + b_off + kB);
                ldsm4(b[4], b[5], b[6], b[7], Bt + b_off + 16 * RS_B + kB);
#pragma unroll
                for (int mb = 0; mb < 4; mb++)
#pragma unroll
                    for (int nb = 0; nb < 4; nb++)
                        mma16816(acc[mb][nb], a[mb][0], a[mb][1], a[mb][2], a[mb][3],
                                 b[2 * nb], b[2 * nb + 1]);
            }
        }
        __syncthreads();

        const int cn = c + GSTAGES;
        if (cn < NC) {
            const uint32_t stg2 = sb + s * GSTAGE3_B;
            tile_cp(stg2,               A,  bm, cn * GBK, K, tid);
            tile_cp(stg2 + GTILE_B,     Bh, bn, cn * GBK, K, tid);
            tile_cp(stg2 + 2 * GTILE_B, Bl, bn, cn * GBK, K, tid);
        }
        asm volatile("cp.async.commit_group;" ::: "memory");

        if (++s == GSTAGES) s = 0;
    }

    const int tr = lane >> 2;
    const int tc = (lane & 3) * 2;
#pragma unroll
    for (int mb = 0; mb < 4; mb++) {
        const int row = bm + wm * 64 + mb * 16 + tr;
#pragma unroll
        for (int nb = 0; nb < 4; nb++) {
            const int col = bn + wn * 32 + nb * 8 + tc;
            float* c0 = C + (size_t)row * N + col;
            *(float2*)c0 = make_float2(acc[mb][nb][0] * W_UNSCALE,
                                       acc[mb][nb][1] * W_UNSCALE);
            float* c1 = C + (size_t)(row + 8) * N + col;
            *(float2*)c1 = make_float2(acc[mb][nb][2] * W_UNSCALE,
                                       acc[mb][nb][3] * W_UNSCALE);
        }
    }
}

// ---------------------------------------------------------------------------
// 1-pass GEMM: C = A @ B^T  (templated output type: float or __half)
// ---------------------------------------------------------------------------
template <typename TOut>
__global__ __launch_bounds__(256, 2)
void gemm_f16_t(const __half* __restrict__ A, const __half* __restrict__ B,
                TOut* __restrict__ C, int M, int N, int K) {
    extern __shared__ __align__(16) char smraw[];
    const uint32_t sb  = smem_u32(smraw);
    const int tid  = threadIdx.x;
    const int wid  = tid >> 5;
    const int lane = tid & 31;
    const int wm   = wid >> 2;
    const int wn   = wid & 3;
    const int bm = blockIdx.y * 128;
    const int bn = blockIdx.x * 128;

    const int a_row = wm * 64 + (lane & 15);
    const int a_colB = ((lane >> 4) * 8) * 2;
    const int b_row = wn * 32 + (lane & 7) + ((lane >> 4) * 8);
    const int b_colB = (((lane >> 3) & 1) * 8) * 2;
    const uint32_t a_off = (uint32_t)(a_row * RS_B + a_colB);
    const uint32_t b_off = (uint32_t)(b_row * RS_B + b_colB);

    float acc[4][4][4];
#pragma unroll
    for (int i = 0; i < 4; i++)
#pragma unroll
        for (int j = 0; j < 4; j++)
#pragma unroll
            for (int k = 0; k < 4; k++) acc[i][j][k] = 0.f;

    const int NC = K / GBK;

#pragma unroll
    for (int i = 0; i < GSTAGES; i++) {
        const uint32_t stg = sb + i * GSTAGE2_B;
        tile_cp(stg,           A, bm, i * GBK, K, tid);
        tile_cp(stg + GTILE_B, B, bn, i * GBK, K, tid);
        asm volatile("cp.async.commit_group;" ::: "memory");
    }

    int s = 0;
    for (int c = 0; c < NC; c++) {
        asm volatile("cp.async.wait_group %0;" :: "n"(GSTAGES - 1) : "memory");
        __syncthreads();

        const uint32_t stg = sb + s * GSTAGE2_B;
        const uint32_t Bt  = stg + GTILE_B;
#pragma unroll
        for (int k16 = 0; k16 < 2; k16++) {
            const uint32_t kB = (uint32_t)(k16 * 16 * 2);
            uint32_t a[4][4];
#pragma unroll
            for (int mb = 0; mb < 4; mb++)
                ldsm4(a[mb][0], a[mb][1], a[mb][2], a[mb][3],
                      stg + a_off + mb * (16 * RS_B) + kB);
            uint32_t b[8];
            ldsm4(b[0], b[1], b[2], b[3], Bt + b_off + kB);
            ldsm4(b[4], b[5], b[6], b[7], Bt + b_off + 16 * RS_B + kB);
#pragma unroll
            for (int mb = 0; mb < 4; mb++)
#pragma unroll
                for (int nb = 0; nb < 4; nb++)
                    mma16816(acc[mb][nb], a[mb][0], a[mb][1], a[mb][2], a[mb][3],
                             b[2 * nb], b[2 * nb + 1]);
        }
        __syncthreads();

        const int cn = c + GSTAGES;
        if (cn < NC) {
            const uint32_t stg2 = sb + s * GSTAGE2_B;
            tile_cp(stg2,           A, bm, cn * GBK, K, tid);
            tile_cp(stg2 + GTILE_B, B, bn, cn * GBK, K, tid);
        }
        asm volatile("cp.async.commit_group;" ::: "memory");

        if (++s == GSTAGES) s = 0;
    }

    const int tr = lane >> 2;
    const int tc = (lane & 3) * 2;
#pragma unroll
    for (int mb = 0; mb < 4; mb++) {
        const int row = bm + wm * 64 + mb * 16 + tr;
#pragma unroll
        for (int nb = 0; nb < 4; nb++) {
            const int col = bn + wn * 32 + nb * 8 + tc;
            if (sizeof(TOut) == 4) {
                float* c0 = (float*)C + (size_t)row * N + col;
                *(float2*)c0 = make_float2(acc[mb][nb][0], acc[mb][nb][1]);
                float* c1 = (float*)C + (size_t)(row + 8) * N + col;
                *(float2*)c1 = make_float2(acc[mb][nb][2], acc[mb][nb][3]);
            } else {
                __half* c0 = (__half*)C + (size_t)row * N + col;
                *(__half2*)c0 = __floats2half2_rn(acc[mb][nb][0], acc[mb][nb][1]);
                __half* c1 = (__half*)C + (size_t)(row + 8) * N + col;
                *(__half2*)c1 = __floats2half2_rn(acc[mb][nb][2], acc[mb][nb][3]);
            }
        }
    }
}

// ---------------------------------------------------------------------------
// HMMA flash attention: 64q x 64k tiles, 4 warps, online softmax in regs.
// Q/K/V fp16, O written fp16 at [s][h*128+d].
// ---------------------------------------------------------------------------
#define AKS 136                               // half stride (272 B) per row
#define ATTN_SMEM_BYTES (5 * 64 * AKS * 2 + 256)

static __device__ __forceinline__ void attn_load_kv(
        uint32_t uK, uint32_t uV,
        const __half* __restrict__ Kh, const __half* __restrict__ Vh,
        int k0, int kvh, int tid) {
#pragma unroll
    for (int i = 0; i < 8; i++) {
        int ch = tid + i * 128;
        int r  = ch >> 4;
        int c  = ch & 15;
        size_t goff = (size_t)(k0 + r) * (HKV * HD) + kvh * HD + c * 8;
        uint32_t soff = (uint32_t)(r * AKS + c * 8) * 2;
        asm volatile("cp.async.cg.shared.global [%0], [%1], 16;"
                     :: "r"(uK + soff), "l"((const void*)(Kh + goff)) : "memory");
        asm volatile("cp.async.cg.shared.global [%0], [%1], 16;"
                     :: "r"(uV + soff), "l"((const void*)(Vh + goff)) : "memory");
    }
}

__global__ __launch_bounds__(128, 2)
void attn_hmma(const __half* __restrict__ Qh, const __half* __restrict__ Kh,
               const __half* __restrict__ Vh, const int* __restrict__ seqlens,
               int nseq, __half* __restrict__ Oh, int S) {
    extern __shared__ __align__(16) char smraw[];
    const uint32_t sb  = smem_u32(smraw);
    const uint32_t uQ  = sb;
    const uint32_t uK0 = sb + 1 * (64 * AKS * 2);
    const uint32_t uV0 = sb + 3 * (64 * AKS * 2);
    int* seg_s = (int*)(smraw + 5 * (64 * AKS * 2));

    const int tid  = threadIdx.x;
    const int wid  = tid >> 5;
    const int lane = tid & 31;
    const int h    = blockIdx.y;
    const int kvh  = h / REP;
    const int qb   = gridDim.x - 1 - (int)blockIdx.x;   // heavy blocks first
    const int q0   = qb * 64;

    // segment start of q0 (all threads; rows sorted => min over block)
    int kt_lo;
    {
        int cum = 0, ss = 0;
        for (int i = 0; i < nseq; i++) {
            int nc = cum + seqlens[i];
            if (q0 < nc) { ss = cum; break; }
            cum = nc;
        }
        kt_lo = ss >> 6;
    }

    // Q tile -> smem
#pragma unroll
    for (int i = 0; i < 8; i++) {
        int ch = tid + i * 128;
        int r  = ch >> 4;
        int c  = ch & 15;
        uint32_t dst = uQ + (uint32_t)(r * AKS + c * 8) * 2;
        const void* g = Qh + (size_t)(q0 + r) * (HQ * HD) + h * HD + c * 8;
        asm volatile("cp.async.cg.shared.global [%0], [%1], 16;"
                     :: "r"(dst), "l"(g) : "memory");
    }
    asm volatile("cp.async.commit_group;" ::: "memory");

    attn_load_kv(uK0, uV0, Kh, Vh, kt_lo * 64, kvh, tid);
    asm volatile("cp.async.commit_group;" ::: "memory");

    // per-row segment starts
    if (tid < 64) {
        int qg = q0 + tid;
        int cum = 0, ss = 0;
        for (int i = 0; i < nseq; i++) {
            int nc = cum + seqlens[i];
            if (qg < nc) { ss = cum; break; }
            cum = nc;
        }
        seg_s[tid] = ss;
    }

    asm volatile("cp.async.wait_group 0;" ::: "memory");
    __syncthreads();

    // Q fragments (held in registers for whole mainloop)
    uint32_t qf[8][4];
    {
        const uint32_t a_off =
            (uint32_t)((wid * 16 + (lane & 15)) * AKS + (lane >> 4) * 8) * 2;
#pragma unroll
        for (int kb = 0; kb < 8; kb++)
            ldsm4(qf[kb][0], qf[kb][1], qf[kb][2], qf[kb][3],
                  uQ + a_off + kb * 32);
    }

    const uint32_t bk_off =
        (uint32_t)(((lane & 7) + ((lane >> 4) * 8)) * AKS + ((lane >> 3) & 1) * 8) * 2;
    const uint32_t bv_off =
        (uint32_t)((lane & 15) * AKS + (lane >> 4) * 8) * 2;

    const int tr  = lane >> 2;
    const int r0l = wid * 16 + tr;
    const int r0g = q0 + r0l;
    const int r1g = r0g + 8;
    const int ss0 = seg_s[r0l];
    const int ss1 = seg_s[r0l + 8];

    float oa[16][4];
#pragma unroll
    for (int i = 0; i < 16; i++)
#pragma unroll
        for (int j = 0; j < 4; j++) oa[i][j] = 0.f;
    float m0 = -1e30f, m1 = -1e30f, l0 = 0.f, l1 = 0.f;

    const int nt = qb - kt_lo + 1;
    int buf = 0;
    for (int t = 0; t < nt; t++) {
        const int k0 = (kt_lo + t) * 64;
        if (t + 1 < nt)
            attn_load_kv(uK0 + (buf ^ 1) * (64 * AKS * 2),
                         uV0 + (buf ^ 1) * (64 * AKS * 2),
                         Kh, Vh, (kt_lo + t + 1) * 64, kvh, tid);
        asm volatile("cp.async.commit_group;" ::: "memory");
        if (t > 0) {
            if (t + 1 < nt)
                asm volatile("cp.async.wait_group 1;" ::: "memory");
            else
                asm volatile("cp.async.wait_group 0;" ::: "memory");
            __syncthreads();
        }

        const uint32_t uKb = uK0 + buf * (64 * AKS * 2);
        const uint32_t uVb = uV0 + buf * (64 * AKS * 2);

        // S = Q @ K^T  (warp tile 16x64)
        float sc[8][4];
#pragma unroll
        for (int i = 0; i < 8; i++)
#pragma unroll
            for (int j = 0; j < 4; j++) sc[i][j] = 0.f;
#pragma unroll
        for (int kb = 0; kb < 8; kb++) {
#pragma unroll
            for (int nbp = 0; nbp < 4; nbp++) {
                uint32_t b0, b1, b2, b3;
                ldsm4(b0, b1, b2, b3,
                      uKb + bk_off + nbp * (16 * AKS * 2) + kb * 32);
                mma16816(sc[2 * nbp],     qf[kb][0], qf[kb][1], qf[kb][2], qf[kb][3], b0, b1);
                mma16816(sc[2 * nbp + 1], qf[kb][0], qf[kb][1], qf[kb][2], qf[kb][3], b2, b3);
            }
        }

        // mask + online softmax
        float mx0 = -1e30f, mx1 = -1e30f;
#pragma unroll
        for (int nb = 0; nb < 8; nb++) {
            int kbase = k0 + nb * 8 + (lane & 3) * 2;
#pragma unroll
            for (int c = 0; c < 2; c++) {
                int kg = kbase + c;
                float v0 = sc[nb][c] * ATT_SCALE;
                float v1 = sc[nb][2 + c] * ATT_SCALE;
                v0 = (kg <= r0g && kg >= ss0) ? v0 : -1e30f;
                v1 = (kg <= r1g && kg >= ss1) ? v1 : -1e30f;
                sc[nb][c] = v0; sc[nb][2 + c] = v1;
                mx0 = fmaxf(mx0, v0); mx1 = fmaxf(mx1, v1);
            }
        }
        mx0 = fmaxf(mx0, __shfl_xor_sync(0xffffffffu, mx0, 1));
        mx0 = fmaxf(mx0, __shfl_xor_sync(0xffffffffu, mx0, 2));
        mx1 = fmaxf(mx1, __shfl_xor_sync(0xffffffffu, mx1, 1));
        mx1 = fmaxf(mx1, __shfl_xor_sync(0xffffffffu, mx1, 2));

        const float m0n = fmaxf(m0, mx0);
        const float m1n = fmaxf(m1, mx1);
        const float al0 = __expf(m0 - m0n);
        const float al1 = __expf(m1 - m1n);

        float s0 = 0.f, s1 = 0.f;
#pragma unroll
        for (int nb = 0; nb < 8; nb++) {
#pragma unroll
            for (int c = 0; c < 2; c++) {
                float p0 = __expf(sc[nb][c]     - m0n);
                float p1 = __expf(sc[nb][2 + c] - m1n);
                sc[nb][c] = p0; sc[nb][2 + c] = p1;
                s0 += p0; s1 += p1;
            }
        }
        s0 += __shfl_xor_sync(0xffffffffu, s0, 1);
        s0 += __shfl_xor_sync(0xffffffffu, s0, 2);
        s1 += __shfl_xor_sync(0xffffffffu, s1, 1);
        s1 += __shfl_xor_sync(0xffffffffu, s1, 2);
        l0 = l0 * al0 + s0;
        l1 = l1 * al1 + s1;
        m0 = m0n; m1 = m1n;

#pragma unroll
        for (int nb = 0; nb < 16; nb++) {
            oa[nb][0] *= al0; oa[nb][1] *= al0;
            oa[nb][2] *= al1; oa[nb][3] *= al1;
        }

        // O += P @ V   (P frags via C->A layout identity; V via ldsm.trans)
#pragma unroll
        for (int kb2 = 0; kb2 < 4; kb2++) {
            uint32_t pf0 = pack_h2(sc[2 * kb2][0],     sc[2 * kb2][1]);
            uint32_t pf1 = pack_h2(sc[2 * kb2][2],     sc[2 * kb2][3]);
            uint32_t pf2 = pack_h2(sc[2 * kb2 + 1][0], sc[2 * kb2 + 1][1]);
            uint32_t pf3 = pack_h2(sc[2 * kb2 + 1][2], sc[2 * kb2 + 1][3]);
#pragma unroll
            for (int nbp = 0; nbp < 8; nbp++) {
                uint32_t b0, b1, b2, b3;
                ldsm4t(b0, b1, b2, b3,
                       uVb + bv_off + kb2 * (16 * AKS * 2) + nbp * 32);
                mma16816(oa[2 * nbp],     pf0, pf1, pf2, pf3, b0, b1);
                mma16816(oa[2 * nbp + 1], pf0, pf1, pf2, pf3, b2, b3);
            }
        }

        __syncthreads();   // compute done before next prefetch overwrites
        buf ^= 1;
    }

    // write O (fp16), layout [s][h*128+d]
    const float inv0 = 1.f / l0;
    const float inv1 = 1.f / l1;
    __half* orow0 = Oh + (size_t)r0g * (HQ * HD) + h * HD;
    __half* orow1 = Oh + (size_t)r1g * (HQ * HD) + h * HD;
#pragma unroll
    for (int nb = 0; nb < 16; nb++) {
        int col = nb * 8 + (lane & 3) * 2;
        *(__half2*)(orow0 + col) = __floats2half2_rn(oa[nb][0] * inv0, oa[nb][1] * inv0);
        *(__half2*)(orow1 + col) = __floats2half2_rn(oa[nb][2] * inv1, oa[nb][3] * inv1);
    }
}

// ---------------------------------------------------------------------------
// Launch
// Inputs: 0:x[S,4096] 1:freqs_cis[S,64,2] 2:seqlens[int32 x nseq]
//         3:wq[4096,4096] 4:wk[1024,4096] 5:wv[1024,4096] 6:wo[4096,4096]
// Output: float32 [S, 4096]
// ---------------------------------------------------------------------------
extern "C" void kernel_launch(void* const* d_in, const int* in_sizes, int n_in,
                              void* d_out, int out_size) {
    const float* x  = (const float*)d_in[0];
    const float* fc = (const float*)d_in[1];
    const int*   sl = (const int*)d_in[2];
    const float* wq = (const float*)d_in[3];
    const float* wk = (const float*)d_in[4];
    const float* wv = (const float*)d_in[5];
    const float* wo = (const float*)d_in[6];
    float* out = (float*)d_out;

    const int S    = in_sizes[0] / DIMK;   // 2048
    const int nseq = in_sizes[2];

    float *Qp, *Kp;
    cudaGetSymbolAddress((void**)&Qp, g_Q);
    cudaGetSymbolAddress((void**)&Kp, g_K);

    __half *xh, *oh, *qh, *kh, *vh, *wqh, *wql, *wkh, *wkl, *wvh, *woh;
    cudaGetSymbolAddress((void**)&xh,  g_xh);
    cudaGetSymbolAddress((void**)&oh,  g_oh);
    cudaGetSymbolAddress((void**)&qh,  g_qh);
    cudaGetSymbolAddress((void**)&kh,  g_kh);
    cudaGetSymbolAddress((void**)&vh,  g_vh);
    cudaGetSymbolAddress((void**)&wqh, g_wqh);
    cudaGetSymbolAddress((void**)&wql, g_wql);
    cudaGetSymbolAddress((void**)&wkh, g_wkh);
    cudaGetSymbolAddress((void**)&wkl, g_wkl);
    cudaGetSymbolAddress((void**)&wvh, g_wvh);
    cudaGetSymbolAddress((void**)&woh, g_woh);

    cudaFuncSetAttribute(gemm_f16x2, cudaFuncAttributeMaxDynamicSharedMemorySize,
                         GSMEM3_BYTES);
    cudaFuncSetAttribute(gemm_f16_t<float>, cudaFuncAttributeMaxDynamicSharedMemorySize,
                         GSMEM2_BYTES);
    cudaFuncSetAttribute(gemm_f16_t<__half>, cudaFuncAttributeMaxDynamicSharedMemorySize,
                         GSMEM2_BYTES);
    cudaFuncSetAttribute(attn_hmma, cudaFuncAttributeMaxDynamicSharedMemorySize,
                         ATTN_SMEM_BYTES);

    // Cast activations; split wq/wk (scaled), cast wv/wo (plain fp16)
    {
        int n;
        n = S * DIMK;       cast_kernel<<<(n / 4 + 255) / 256, 256>>>(x, xh, n / 4);
        n = 4096 * 4096;    split_w_kernel<<<(n / 4 + 255) / 256, 256>>>(wq, wqh, wql, n / 4);
        n = 1024 * 4096;    split_w_kernel<<<(n / 4 + 255) / 256, 256>>>(wk, wkh, wkl, n / 4);
        n = 1024 * 4096;    cast_kernel<<<(n / 4 + 255) / 256, 256>>>(wv, wvh, n / 4);
        n = 4096 * 4096;    cast_kernel<<<(n / 4 + 255) / 256, 256>>>(wo, woh, n / 4);
    }

    // QKV projections (Q,K fp32 out for rope; V fp16 out directly)
    gemm_f16x2<<<dim3(4096 / 128, S / 128), 256, GSMEM3_BYTES>>>(xh, wqh, wql, Qp, S, 4096, DIMK);
    gemm_f16x2<<<dim3(1024 / 128, S / 128), 256, GSMEM3_BYTES>>>(xh, wkh, wkl, Kp, S, 1024, DIMK);
    gemm_f16_t<__half><<<dim3(1024 / 128, S / 128), 256, GSMEM2_BYTES>>>(xh, wvh, vh, S, 1024, DIMK);

    // RoPE + cast to fp16
    {
        int tq = S * HQ * (HD / 2);
        rope_cast_kernel<<<(tq + 255) / 256, 256>>>(Qp, fc, qh, S, HQ);
        int tk = S * HKV * (HD / 2);
        rope_cast_kernel<<<(tk + 255) / 256, 256>>>(Kp, fc, kh, S, HKV);
    }

    // Attention (HMMA, fp16 in/out)
    attn_hmma<<<dim3(S / 64, HQ), 128, ATTN_SMEM_BYTES>>>(qh, kh, vh, sl, nseq, oh, S);

    // Output projection (single-pass fp16)
    gemm_f16_t<float><<<dim3(4096 / 128, S / 128), 256, GSMEM2_BYTES>>>(oh, woh, out, S, 4096, DIMK);
}

// round 11
// speedup vs baseline: 1.2278x; 1.2278x over previous
#include <cuda_runtime.h>
#include <cuda_fp16.h>
#include <math.h>
#include <stdint.h>

// Problem constants
#define DIMK 4096
#define HQ   32
#define HKV  8
#define HD   128
#define REP  (HQ / HKV)
#define SMAX 2048
#define ATT_SCALE 0.08838834764831845f   // 1/sqrt(128)
#define W_SCALE   1024.0f
#define W_UNSCALE 0.0009765625f          // 2^-10

// ---------------------------------------------------------------------------
// Scratch (device globals: allocation-free per harness rules)
// ---------------------------------------------------------------------------
__device__ __half g_xh[(size_t)SMAX * DIMK];
__device__ __half g_oh[(size_t)SMAX * DIMK];     // attention output (fp16)
__device__ __half g_qh[(size_t)SMAX * HQ * HD];  // fp16 Q (roped, from GEMM)
__device__ __half g_kh[(size_t)SMAX * HKV * HD]; // fp16 K (roped, from GEMM)
__device__ __half g_vh[(size_t)SMAX * HKV * HD]; // fp16 V
__device__ __half g_wqh[(size_t)4096 * 4096];    // plain fp16 (single-pass)
__device__ __half g_wkh[(size_t)1024 * 4096];    // scaled x1024, hi
__device__ __half g_wkl[(size_t)1024 * 4096];    // scaled x1024, lo
__device__ __half g_wvh[(size_t)1024 * 4096];    // plain fp16 (single-pass)
__device__ __half g_woh[(size_t)4096 * 4096];    // plain fp16 (single-pass)

// ---------------------------------------------------------------------------
// Helpers
// ---------------------------------------------------------------------------
static __device__ __forceinline__ uint32_t smem_u32(const void* p) {
    uint32_t a;
    asm("{ .reg .u64 t; cvta.to.shared.u64 t, %1; cvt.u32.u64 %0, t; }"
        : "=r"(a) : "l"(p));
    return a;
}

static __device__ __forceinline__ void ldsm4(uint32_t& r0, uint32_t& r1,
                                             uint32_t& r2, uint32_t& r3,
                                             uint32_t addr) {
    asm volatile("ldmatrix.sync.aligned.m8n8.x4.shared.b16 {%0,%1,%2,%3}, [%4];"
                 : "=r"(r0), "=r"(r1), "=r"(r2), "=r"(r3) : "r"(addr));
}

static __device__ __forceinline__ void ldsm4t(uint32_t& r0, uint32_t& r1,
                                              uint32_t& r2, uint32_t& r3,
                                              uint32_t addr) {
    asm volatile("ldmatrix.sync.aligned.m8n8.x4.trans.shared.b16 {%0,%1,%2,%3}, [%4];"
                 : "=r"(r0), "=r"(r1), "=r"(r2), "=r"(r3) : "r"(addr));
}

static __device__ __forceinline__ void mma16816(float* c, uint32_t a0, uint32_t a1,
                                                uint32_t a2, uint32_t a3,
                                                uint32_t b0, uint32_t b1) {
    asm volatile(
        "mma.sync.aligned.m16n8k16.row.col.f32.f16.f16.f32 "
        "{%0,%1,%2,%3}, {%4,%5,%6,%7}, {%8,%9}, {%0,%1,%2,%3};"
        : "+f"(c[0]), "+f"(c[1]), "+f"(c[2]), "+f"(c[3])
        : "r"(a0), "r"(a1), "r"(a2), "r"(a3), "r"(b0), "r"(b1));
}

static __device__ __forceinline__ uint32_t pack_h2(float a, float b) {
    __half2 h = __floats2half2_rn(a, b);
    return *(uint32_t*)&h;
}

// rotate (v0,v1) by (cos,sin), round to half2
static __device__ __forceinline__ __half2 rope_h2(float v0, float v1, float2 cs) {
    return __floats2half2_rn(v0 * cs.x - v1 * cs.y, v0 * cs.y + v1 * cs.x);
}

// ---------------------------------------------------------------------------
// Cast fp32 -> fp16.  n % 4 == 0.
// ---------------------------------------------------------------------------
__global__ void cast_kernel(const float* __restrict__ X,
                            __half* __restrict__ H, int n4) {
    int i = blockIdx.x * blockDim.x + threadIdx.x;
    if (i >= n4) return;
    float4 v = ((const float4*)X)[i];
    __half2* Hp = (__half2*)H;
    Hp[2 * i]     = __floats2half2_rn(v.x, v.y);
    Hp[2 * i + 1] = __floats2half2_rn(v.z, v.w);
}

// ---------------------------------------------------------------------------
// Split fp32 weight -> (fp16 hi, fp16 lo), pre-scaled by 1024 (subnormal guard)
// ---------------------------------------------------------------------------
__global__ void split_w_kernel(const float* __restrict__ X,
                               __half* __restrict__ H,
                               __half* __restrict__ L, int n4) {
    int i = blockIdx.x * blockDim.x + threadIdx.x;
    if (i >= n4) return;
    float4 v = ((const float4*)X)[i];
    float sx = v.x * W_SCALE, sy = v.y * W_SCALE;
    float sz = v.z * W_SCALE, sw = v.w * W_SCALE;
    __half hx = __float2half_rn(sx);
    __half hy = __float2half_rn(sy);
    __half hz = __float2half_rn(sz);
    __half hw = __float2half_rn(sw);
    __half lx = __float2half_rn(sx - __half2float(hx));
    __half ly = __float2half_rn(sy - __half2float(hy));
    __half lz = __float2half_rn(sz - __half2float(hz));
    __half lw = __float2half_rn(sw - __half2float(hw));
    __half2* Hp = (__half2*)H;
    __half2* Lp = (__half2*)L;
    Hp[2 * i]     = __half2(hx, hy);
    Hp[2 * i + 1] = __half2(hz, hw);
    Lp[2 * i]     = __half2(lx, ly);
    Lp[2 * i + 1] = __half2(lz, lw);
}

// ---------------------------------------------------------------------------
// Shared GEMM geometry: 128x128 CTA tile, BK=32, 8 warps (2x4), warp 64x32.
// ---------------------------------------------------------------------------
#define GSTAGES 3
#define GBK     32
#define RS_B    80
#define GTILE_B (128 * RS_B)
#define GSTAGE3_B (3 * GTILE_B)
#define GSMEM3_BYTES (GSTAGES * GSTAGE3_B)
#define GSTAGE2_B (2 * GTILE_B)
#define GSMEM2_BYTES (GSTAGES * GSTAGE2_B)

static __device__ __forceinline__ void tile_cp(uint32_t sbase,
        const __half* __restrict__ src, int r0, int kc, int K, int tid) {
#pragma unroll
    for (int i = 0; i < 2; i++) {
        int ch  = tid + i * 256;
        int r   = ch >> 2;
        int c16 = ch & 3;
        uint32_t dst = sbase + (uint32_t)(r * RS_B + c16 * 16);
        const void* g = src + (size_t)(r0 + r) * K + kc + c16 * 8;
        asm volatile("cp.async.cg.shared.global [%0], [%1], 16;"
                     :: "r"(dst), "l"(g) : "memory");
    }
}

// ---------------------------------------------------------------------------
// 2-pass GEMM + fused RoPE: Kout = rope((1/1024) * A @ (Bh+Bl)^T), fp16 out.
// ---------------------------------------------------------------------------
__global__ __launch_bounds__(256, 2)
void gemm_f16x2_rope(const __half* __restrict__ A, const __half* __restrict__ Bh,
                     const __half* __restrict__ Bl, const float* __restrict__ fc,
                     __half* __restrict__ C, int M, int N, int K) {
    extern __shared__ __align__(16) char smraw[];
    const uint32_t sb  = smem_u32(smraw);
    const int tid  = threadIdx.x;
    const int wid  = tid >> 5;
    const int lane = tid & 31;
    const int wm   = wid >> 2;
    const int wn   = wid & 3;
    const int bm = blockIdx.y * 128;
    const int bn = blockIdx.x * 128;

    const int a_row = wm * 64 + (lane & 15);
    const int a_colB = ((lane >> 4) * 8) * 2;
    const int b_row = wn * 32 + (lane & 7) + ((lane >> 4) * 8);
    const int b_colB = (((lane >> 3) & 1) * 8) * 2;
    const uint32_t a_off = (uint32_t)(a_row * RS_B + a_colB);
    const uint32_t b_off = (uint32_t)(b_row * RS_B + b_colB);

    float acc[4][4][4];
#pragma unroll
    for (int i = 0; i < 4; i++)
#pragma unroll
        for (int j = 0; j < 4; j++)
#pragma unroll
            for (int k = 0; k < 4; k++) acc[i][j][k] = 0.f;

    const int NC = K / GBK;

#pragma unroll
    for (int i = 0; i < GSTAGES; i++) {
        const uint32_t stg = sb + i * GSTAGE3_B;
        tile_cp(stg,               A,  bm, i * GBK, K, tid);
        tile_cp(stg + GTILE_B,     Bh, bn, i * GBK, K, tid);
        tile_cp(stg + 2 * GTILE_B, Bl, bn, i * GBK, K, tid);
        asm volatile("cp.async.commit_group;" ::: "memory");
    }

    int s = 0;
    for (int c = 0; c < NC; c++) {
        asm volatile("cp.async.wait_group %0;" :: "n"(GSTAGES - 1) : "memory");
        __syncthreads();

        const uint32_t stg = sb + s * GSTAGE3_B;
#pragma unroll
        for (int k16 = 0; k16 < 2; k16++) {
            const uint32_t kB = (uint32_t)(k16 * 16 * 2);
            uint32_t a[4][4];
#pragma unroll
            for (int mb = 0; mb < 4; mb++)
                ldsm4(a[mb][0], a[mb][1], a[mb][2], a[mb][3],
                      stg + a_off + mb * (16 * RS_B) + kB);
#pragma unroll
            for (int p = 0; p < 2; p++) {
                const uint32_t Bt = stg + (1 + p) * GTILE_B;
                uint32_t b[8];
                ldsm4(b[0], b[1], b[2], b[3], Bt + b_off + kB);
                ldsm4(b[4], b[5], b[6], b[7], Bt + b_off + 16 * RS_B + kB);
#pragma unroll
                for (int mb = 0; mb < 4; mb++)
#pragma unroll
                    for (int nb = 0; nb < 4; nb++)
                        mma16816(acc[mb][nb], a[mb][0], a[mb][1], a[mb][2], a[mb][3],
                                 b[2 * nb], b[2 * nb + 1]);
            }
        }
        __syncthreads();

        const int cn = c + GSTAGES;
        if (cn < NC) {
            const uint32_t stg2 = sb + s * GSTAGE3_B;
            tile_cp(stg2,               A,  bm, cn * GBK, K, tid);
            tile_cp(stg2 + GTILE_B,     Bh, bn, cn * GBK, K, tid);
            tile_cp(stg2 + 2 * GTILE_B, Bl, bn, cn * GBK, K, tid);
        }
        asm volatile("cp.async.commit_group;" ::: "memory");

        if (++s == GSTAGES) s = 0;
    }

    const int tr = lane >> 2;
    const int tc = (lane & 3) * 2;
#pragma unroll
    for (int mb = 0; mb < 4; mb++) {
        const int row0 = bm + wm * 64 + mb * 16 + tr;
        const int row1 = row0 + 8;
#pragma unroll
        for (int nb = 0; nb < 4; nb++) {
            const int col = bn + wn * 32 + nb * 8 + tc;
            const int d = col & (HD - 1);
            float2 cs0 = *(const float2*)(fc + (size_t)row0 * HD + d);
            float2 cs1 = *(const float2*)(fc + (size_t)row1 * HD + d);
            float v00 = acc[mb][nb][0] * W_UNSCALE;
            float v01 = acc[mb][nb][1] * W_UNSCALE;
            float v10 = acc[mb][nb][2] * W_UNSCALE;
            float v11 = acc[mb][nb][3] * W_UNSCALE;
            *(__half2*)(C + (size_t)row0 * N + col) = rope_h2(v00, v01, cs0);
            *(__half2*)(C + (size_t)row1 * N + col) = rope_h2(v10, v11, cs1);
        }
    }
}

// ---------------------------------------------------------------------------
// 1-pass GEMM: C = A @ B^T.  ROPE: fuse RoPE in epilogue (fp16 out only).
// TOut: float or __half.
// ---------------------------------------------------------------------------
template <typename TOut, bool ROPE>
__global__ __launch_bounds__(256, 2)
void gemm_f16_t(const __half* __restrict__ A, const __half* __restrict__ B,
                TOut* __restrict__ C, const float* __restrict__ fc,
                int M, int N, int K) {
    extern __shared__ __align__(16) char smraw[];
    const uint32_t sb  = smem_u32(smraw);
    const int tid  = threadIdx.x;
    const int wid  = tid >> 5;
    const int lane = tid & 31;
    const int wm   = wid >> 2;
    const int wn   = wid & 3;
    const int bm = blockIdx.y * 128;
    const int bn = blockIdx.x * 128;

    const int a_row = wm * 64 + (lane & 15);
    const int a_colB = ((lane >> 4) * 8) * 2;
    const int b_row = wn * 32 + (lane & 7) + ((lane >> 4) * 8);
    const int b_colB = (((lane >> 3) & 1) * 8) * 2;
    const uint32_t a_off = (uint32_t)(a_row * RS_B + a_colB);
    const uint32_t b_off = (uint32_t)(b_row * RS_B + b_colB);

    float acc[4][4][4];
#pragma unroll
    for (int i = 0; i < 4; i++)
#pragma unroll
        for (int j = 0; j < 4; j++)
#pragma unroll
            for (int k = 0; k < 4; k++) acc[i][j][k] = 0.f;

    const int NC = K / GBK;

#pragma unroll
    for (int i = 0; i < GSTAGES; i++) {
        const uint32_t stg = sb + i * GSTAGE2_B;
        tile_cp(stg,           A, bm, i * GBK, K, tid);
        tile_cp(stg + GTILE_B, B, bn, i * GBK, K, tid);
        asm volatile("cp.async.commit_group;" ::: "memory");
    }

    int s = 0;
    for (int c = 0; c < NC; c++) {
        asm volatile("cp.async.wait_group %0;" :: "n"(GSTAGES - 1) : "memory");
        __syncthreads();

        const uint32_t stg = sb + s * GSTAGE2_B;
        const uint32_t Bt  = stg + GTILE_B;
#pragma unroll
        for (int k16 = 0; k16 < 2; k16++) {
            const uint32_t kB = (uint32_t)(k16 * 16 * 2);
            uint32_t a[4][4];
#pragma unroll
            for (int mb = 0; mb < 4; mb++)
                ldsm4(a[mb][0], a[mb][1], a[mb][2], a[mb][3],
                      stg + a_off + mb * (16 * RS_B) + kB);
            uint32_t b[8];
            ldsm4(b[0], b[1], b[2], b[3], Bt + b_off + kB);
            ldsm4(b[4], b[5], b[6], b[7], Bt + b_off + 16 * RS_B + kB);
#pragma unroll
            for (int mb = 0; mb < 4; mb++)
#pragma unroll
                for (int nb = 0; nb < 4; nb++)
                    mma16816(acc[mb][nb], a[mb][0], a[mb][1], a[mb][2], a[mb][3],
                             b[2 * nb], b[2 * nb + 1]);
        }
        __syncthreads();

        const int cn = c + GSTAGES;
        if (cn < NC) {
            const uint32_t stg2 = sb + s * GSTAGE2_B;
            tile_cp(stg2,           A, bm, cn * GBK, K, tid);
            tile_cp(stg2 + GTILE_B, B, bn, cn * GBK, K, tid);
        }
        asm volatile("cp.async.commit_group;" ::: "memory");

        if (++s == GSTAGES) s = 0;
    }

    const int tr = lane >> 2;
    const int tc = (lane & 3) * 2;
#pragma unroll
    for (int mb = 0; mb < 4; mb++) {
        const int row0 = bm + wm * 64 + mb * 16 + tr;
        const int row1 = row0 + 8;
#pragma unroll
        for (int nb = 0; nb < 4; nb++) {
            const int col = bn + wn * 32 + nb * 8 + tc;
            if (ROPE) {
                const int d = col & (HD - 1);
                float2 cs0 = *(const float2*)(fc + (size_t)row0 * HD + d);
                float2 cs1 = *(const float2*)(fc + (size_t)row1 * HD + d);
                *(__half2*)((__half*)C + (size_t)row0 * N + col) =
                    rope_h2(acc[mb][nb][0], acc[mb][nb][1], cs0);
                *(__half2*)((__half*)C + (size_t)row1 * N + col) =
                    rope_h2(acc[mb][nb][2], acc[mb][nb][3], cs1);
            } else if (sizeof(TOut) == 4) {
                float* c0 = (float*)C + (size_t)row0 * N + col;
                *(float2*)c0 = make_float2(acc[mb][nb][0], acc[mb][nb][1]);
                float* c1 = (float*)C + (size_t)row1 * N + col;
                *(float2*)c1 = make_float2(acc[mb][nb][2], acc[mb][nb][3]);
            } else {
                __half* c0 = (__half*)C + (size_t)row0 * N + col;
                *(__half2*)c0 = __floats2half2_rn(acc[mb][nb][0], acc[mb][nb][1]);
                __half* c1 = (__half*)C + (size_t)row1 * N + col;
                *(__half2*)c1 = __floats2half2_rn(acc[mb][nb][2], acc[mb][nb][3]);
            }
        }
    }
}

// ---------------------------------------------------------------------------
// HMMA flash attention: 64q x 64k tiles, 4 warps, online softmax in regs.
// Q/K/V fp16, O written fp16 at [s][h*128+d].
// ---------------------------------------------------------------------------
#define AKS 136                               // half stride (272 B) per row
#define ATTN_SMEM_BYTES (5 * 64 * AKS * 2 + 256)

static __device__ __forceinline__ void attn_load_kv(
        uint32_t uK, uint32_t uV,
        const __half* __restrict__ Kh, const __half* __restrict__ Vh,
        int k0, int kvh, int tid) {
#pragma unroll
    for (int i = 0; i < 8; i++) {
        int ch = tid + i * 128;
        int r  = ch >> 4;
        int c  = ch & 15;
        size_t goff = (size_t)(k0 + r) * (HKV * HD) + kvh * HD + c * 8;
        uint32_t soff = (uint32_t)(r * AKS + c * 8) * 2;
        asm volatile("cp.async.cg.shared.global [%0], [%1], 16;"
                     :: "r"(uK + soff), "l"((const void*)(Kh + goff)) : "memory");
        asm volatile("cp.async.cg.shared.global [%0], [%1], 16;"
                     :: "r"(uV + soff), "l"((const void*)(Vh + goff)) : "memory");
    }
}

__global__ __launch_bounds__(128, 2)
void attn_hmma(const __half* __restrict__ Qh, const __half* __restrict__ Kh,
               const __half* __restrict__ Vh, const int* __restrict__ seqlens,
               int nseq, __half* __restrict__ Oh, int S) {
    extern __shared__ __align__(16) char smraw[];
    const uint32_t sb  = smem_u32(smraw);
    const uint32_t uQ  = sb;
    const uint32_t uK0 = sb + 1 * (64 * AKS * 2);
    const uint32_t uV0 = sb + 3 * (64 * AKS * 2);
    int* seg_s = (int*)(smraw + 5 * (64 * AKS * 2));

    const int tid  = threadIdx.x;
    const int wid  = tid >> 5;
    const int lane = tid & 31;
    const int h    = blockIdx.y;
    const int kvh  = h / REP;
    const int qb   = gridDim.x - 1 - (int)blockIdx.x;   // heavy blocks first
    const int q0   = qb * 64;

    int kt_lo;
    {
        int cum = 0, ss = 0;
        for (int i = 0; i < nseq; i++) {
            int nc = cum + seqlens[i];
            if (q0 < nc) { ss = cum; break; }
            cum = nc;
        }
        kt_lo = ss >> 6;
    }

    // Q tile -> smem
#pragma unroll
    for (int i = 0; i < 8; i++) {
        int ch = tid + i * 128;
        int r  = ch >> 4;
        int c  = ch & 15;
        uint32_t dst = uQ + (uint32_t)(r * AKS + c * 8) * 2;
        const void* g = Qh + (size_t)(q0 + r) * (HQ * HD) + h * HD + c * 8;
        asm volatile("cp.async.cg.shared.global [%0], [%1], 16;"
                     :: "r"(dst), "l"(g) : "memory");
    }
    asm volatile("cp.async.commit_group;" ::: "memory");

    attn_load_kv(uK0, uV0, Kh, Vh, kt_lo * 64, kvh, tid);
    asm volatile("cp.async.commit_group;" ::: "memory");

    if (tid < 64) {
        int qg = q0 + tid;
        int cum = 0, ss = 0;
        for (int i = 0; i < nseq; i++) {
            int nc = cum + seqlens[i];
            if (qg < nc) { ss = cum; break; }
            cum = nc;
        }
        seg_s[tid] = ss;
    }

    asm volatile("cp.async.wait_group 0;" ::: "memory");
    __syncthreads();

    uint32_t qf[8][4];
    {
        const uint32_t a_off =
            (uint32_t)((wid * 16 + (lane & 15)) * AKS + (lane >> 4) * 8) * 2;
#pragma unroll
        for (int kb = 0; kb < 8; kb++)
            ldsm4(qf[kb][0], qf[kb][1], qf[kb][2], qf[kb][3],
                  uQ + a_off + kb * 32);
    }

    const uint32_t bk_off =
        (uint32_t)(((lane & 7) + ((lane >> 4) * 8)) * AKS + ((lane >> 3) & 1) * 8) * 2;
    const uint32_t bv_off =
        (uint32_t)((lane & 15) * AKS + (lane >> 4) * 8) * 2;

    const int tr  = lane >> 2;
    const int r0l = wid * 16 + tr;
    const int r0g = q0 + r0l;
    const int r1g = r0g + 8;
    const int ss0 = seg_s[r0l];
    const int ss1 = seg_s[r0l + 8];

    float oa[16][4];
#pragma unroll
    for (int i = 0; i < 16; i++)
#pragma unroll
        for (int j = 0; j < 4; j++) oa[i][j] = 0.f;
    float m0 = -1e30f, m1 = -1e30f, l0 = 0.f, l1 = 0.f;

    const int nt = qb - kt_lo + 1;
    int buf = 0;
    for (int t = 0; t < nt; t++) {
        const int k0 = (kt_lo + t) * 64;
        if (t + 1 < nt)
            attn_load_kv(uK0 + (buf ^ 1) * (64 * AKS * 2),
                         uV0 + (buf ^ 1) * (64 * AKS * 2),
                         Kh, Vh, (kt_lo + t + 1) * 64, kvh, tid);
        asm volatile("cp.async.commit_group;" ::: "memory");
        if (t > 0) {
            if (t + 1 < nt)
                asm volatile("cp.async.wait_group 1;" ::: "memory");
            else
                asm volatile("cp.async.wait_group 0;" ::: "memory");
            __syncthreads();
        }

        const uint32_t uKb = uK0 + buf * (64 * AKS * 2);
        const uint32_t uVb = uV0 + buf * (64 * AKS * 2);

        float sc[8][4];
#pragma unroll
        for (int i = 0; i < 8; i++)
#pragma unroll
            for (int j = 0; j < 4; j++) sc[i][j] = 0.f;
#pragma unroll
        for (int kb = 0; kb < 8; kb++) {
#pragma unroll
            for (int nbp = 0; nbp < 4; nbp++) {
                uint32_t b0, b1, b2, b3;
                ldsm4(b0, b1, b2, b3,
                      uKb + bk_off + nbp * (16 * AKS * 2) + kb * 32);
                mma16816(sc[2 * nbp],     qf[kb][0], qf[kb][1], qf[kb][2], qf[kb][3], b0, b1);
                mma16816(sc[2 * nbp + 1], qf[kb][0], qf[kb][1], qf[kb][2], qf[kb][3], b2, b3);
            }
        }

        float mx0 = -1e30f, mx1 = -1e30f;
#pragma unroll
        for (int nb = 0; nb < 8; nb++) {
            int kbase = k0 + nb * 8 + (lane & 3) * 2;
#pragma unroll
            for (int c = 0; c < 2; c++) {
                int kg = kbase + c;
                float v0 = sc[nb][c] * ATT_SCALE;
                float v1 = sc[nb][2 + c] * ATT_SCALE;
                v0 = (kg <= r0g && kg >= ss0) ? v0 : -1e30f;
                v1 = (kg <= r1g && kg >= ss1) ? v1 : -1e30f;
                sc[nb][c] = v0; sc[nb][2 + c] = v1;
                mx0 = fmaxf(mx0, v0); mx1 = fmaxf(mx1, v1);
            }
        }
        mx0 = fmaxf(mx0, __shfl_xor_sync(0xffffffffu, mx0, 1));
        mx0 = fmaxf(mx0, __shfl_xor_sync(0xffffffffu, mx0, 2));
        mx1 = fmaxf(mx1, __shfl_xor_sync(0xffffffffu, mx1, 1));
        mx1 = fmaxf(mx1, __shfl_xor_sync(0xffffffffu, mx1, 2));

        const float m0n = fmaxf(m0, mx0);
        const float m1n = fmaxf(m1, mx1);
        const float al0 = __expf(m0 - m0n);
        const float al1 = __expf(m1 - m1n);

        float s0 = 0.f, s1 = 0.f;
#pragma unroll
        for (int nb = 0; nb < 8; nb++) {
#pragma unroll
            for (int c = 0; c < 2; c++) {
                float p0 = __expf(sc[nb][c]     - m0n);
                float p1 = __expf(sc[nb][2 + c] - m1n);
                sc[nb][c] = p0; sc[nb][2 + c] = p1;
                s0 += p0; s1 += p1;
            }
        }
        s0 += __shfl_xor_sync(0xffffffffu, s0, 1);
        s0 += __shfl_xor_sync(0xffffffffu, s0, 2);
        s1 += __shfl_xor_sync(0xffffffffu, s1, 1);
        s1 += __shfl_xor_sync(0xffffffffu, s1, 2);
        l0 = l0 * al0 + s0;
        l1 = l1 * al1 + s1;
        m0 = m0n; m1 = m1n;

#pragma unroll
        for (int nb = 0; nb < 16; nb++) {
            oa[nb][0] *= al0; oa[nb][1] *= al0;
            oa[nb][2] *= al1; oa[nb][3] *= al1;
        }

#pragma unroll
        for (int kb2 = 0; kb2 < 4; kb2++) {
            uint32_t pf0 = pack_h2(sc[2 * kb2][0],     sc[2 * kb2][1]);
            uint32_t pf1 = pack_h2(sc[2 * kb2][2],     sc[2 * kb2][3]);
            uint32_t pf2 = pack_h2(sc[2 * kb2 + 1][0], sc[2 * kb2 + 1][1]);
            uint32_t pf3 = pack_h2(sc[2 * kb2 + 1][2], sc[2 * kb2 + 1][3]);
#pragma unroll
            for (int nbp = 0; nbp < 8; nbp++) {
                uint32_t b0, b1, b2, b3;
                ldsm4t(b0, b1, b2, b3,
                       uVb + bv_off + kb2 * (16 * AKS * 2) + nbp * 32);
                mma16816(oa[2 * nbp],     pf0, pf1, pf2, pf3, b0, b1);
                mma16816(oa[2 * nbp + 1], pf0, pf1, pf2, pf3, b2, b3);
            }
        }

        __syncthreads();
        buf ^= 1;
    }

    const float inv0 = 1.f / l0;
    const float inv1 = 1.f / l1;
    __half* orow0 = Oh + (size_t)r0g * (HQ * HD) + h * HD;
    __half* orow1 = Oh + (size_t)r1g * (HQ * HD) + h * HD;
#pragma unroll
    for (int nb = 0; nb < 16; nb++) {
        int col = nb * 8 + (lane & 3) * 2;
        *(__half2*)(orow0 + col) = __floats2half2_rn(oa[nb][0] * inv0, oa[nb][1] * inv0);
        *(__half2*)(orow1 + col) = __floats2half2_rn(oa[nb][2] * inv1, oa[nb][3] * inv1);
    }
}

// ---------------------------------------------------------------------------
// Launch
// Inputs: 0:x[S,4096] 1:freqs_cis[S,64,2] 2:seqlens[int32 x nseq]
//         3:wq[4096,4096] 4:wk[1024,4096] 5:wv[1024,4096] 6:wo[4096,4096]
// Output: float32 [S, 4096]
// ---------------------------------------------------------------------------
extern "C" void kernel_launch(void* const* d_in, const int* in_sizes, int n_in,
                              void* d_out, int out_size) {
    const float* x  = (const float*)d_in[0];
    const float* fc = (const float*)d_in[1];
    const int*   sl = (const int*)d_in[2];
    const float* wq = (const float*)d_in[3];
    const float* wk = (const float*)d_in[4];
    const float* wv = (const float*)d_in[5];
    const float* wo = (const float*)d_in[6];
    float* out = (float*)d_out;

    const int S    = in_sizes[0] / DIMK;   // 2048
    const int nseq = in_sizes[2];

    __half *xh, *oh, *qh, *kh, *vh, *wqh, *wkh, *wkl, *wvh, *woh;
    cudaGetSymbolAddress((void**)&xh,  g_xh);
    cudaGetSymbolAddress((void**)&oh,  g_oh);
    cudaGetSymbolAddress((void**)&qh,  g_qh);
    cudaGetSymbolAddress((void**)&kh,  g_kh);
    cudaGetSymbolAddress((void**)&vh,  g_vh);
    cudaGetSymbolAddress((void**)&wqh, g_wqh);
    cudaGetSymbolAddress((void**)&wkh, g_wkh);
    cudaGetSymbolAddress((void**)&wkl, g_wkl);
    cudaGetSymbolAddress((void**)&wvh, g_wvh);
    cudaGetSymbolAddress((void**)&woh, g_woh);

    cudaFuncSetAttribute(gemm_f16x2_rope, cudaFuncAttributeMaxDynamicSharedMemorySize,
                         GSMEM3_BYTES);
    cudaFuncSetAttribute((const void*)gemm_f16_t<float, false>,
                         cudaFuncAttributeMaxDynamicSharedMemorySize, GSMEM2_BYTES);
    cudaFuncSetAttribute((const void*)gemm_f16_t<__half, false>,
                         cudaFuncAttributeMaxDynamicSharedMemorySize, GSMEM2_BYTES);
    cudaFuncSetAttribute((const void*)gemm_f16_t<__half, true>,
                         cudaFuncAttributeMaxDynamicSharedMemorySize, GSMEM2_BYTES);
    cudaFuncSetAttribute(attn_hmma, cudaFuncAttributeMaxDynamicSharedMemorySize,
                         ATTN_SMEM_BYTES);

    // Cast activations + wq/wv/wo (plain fp16); split wk (scaled hi/lo)
    {
        int n;
        n = S * DIMK;       cast_kernel<<<(n / 4 + 255) / 256, 256>>>(x, xh, n / 4);
        n = 4096 * 4096;    cast_kernel<<<(n / 4 + 255) / 256, 256>>>(wq, wqh, n / 4);
        n = 1024 * 4096;    split_w_kernel<<<(n / 4 + 255) / 256, 256>>>(wk, wkh, wkl, n / 4);
        n = 1024 * 4096;    cast_kernel<<<(n / 4 + 255) / 256, 256>>>(wv, wvh, n / 4);
        n = 4096 * 4096;    cast_kernel<<<(n / 4 + 255) / 256, 256>>>(wo, woh, n / 4);
    }

    // QKV projections (RoPE fused into Q and K epilogues; fp16 outputs)
    gemm_f16_t<__half, true><<<dim3(4096 / 128, S / 128), 256, GSMEM2_BYTES>>>(
        xh, wqh, qh, fc, S, 4096, DIMK);
    gemm_f16x2_rope<<<dim3(1024 / 128, S / 128), 256, GSMEM3_BYTES>>>(
        xh, wkh, wkl, fc, kh, S, 1024, DIMK);
    gemm_f16_t<__half, false><<<dim3(1024 / 128, S / 128), 256, GSMEM2_BYTES>>>(
        xh, wvh, vh, nullptr, S, 1024, DIMK);

    // Attention (HMMA, fp16 in/out)
    attn_hmma<<<dim3(S / 64, HQ), 128, ATTN_SMEM_BYTES>>>(qh, kh, vh, sl, nseq, oh, S);

    // Output projection (single-pass fp16, fp32 out)
    gemm_f16_t<float, false><<<dim3(4096 / 128, S / 128), 256, GSMEM2_BYTES>>>(
        oh, woh, out, nullptr, S, 4096, DIMK);
}

// round 12
// speedup vs baseline: 1.3512x; 1.1005x over previous
#include <cuda_runtime.h>
#include <cuda_fp16.h>
#include <math.h>
#include <stdint.h>

// Problem constants
#define DIMK 4096
#define HQ   32
#define HKV  8
#define HD   128
#define REP  (HQ / HKV)
#define SMAX 2048
#define ATT_SCALE 0.08838834764831845f   // 1/sqrt(128)

// ---------------------------------------------------------------------------
// Scratch (device globals: allocation-free per harness rules)
// ---------------------------------------------------------------------------
__device__ __half g_xh[(size_t)SMAX * DIMK];
__device__ __half g_oh[(size_t)SMAX * DIMK];     // attention output (fp16)
__device__ __half g_qh[(size_t)SMAX * HQ * HD];  // fp16 Q (roped, from GEMM)
__device__ __half g_kh[(size_t)SMAX * HKV * HD]; // fp16 K (roped, from GEMM)
__device__ __half g_vh[(size_t)SMAX * HKV * HD]; // fp16 V
__device__ __half g_wqh[(size_t)4096 * 4096];
__device__ __half g_wkh[(size_t)1024 * 4096];
__device__ __half g_wvh[(size_t)1024 * 4096];
__device__ __half g_woh[(size_t)4096 * 4096];

// ---------------------------------------------------------------------------
// Helpers
// ---------------------------------------------------------------------------
static __device__ __forceinline__ uint32_t smem_u32(const void* p) {
    uint32_t a;
    asm("{ .reg .u64 t; cvta.to.shared.u64 t, %1; cvt.u32.u64 %0, t; }"
        : "=r"(a) : "l"(p));
    return a;
}

static __device__ __forceinline__ void ldsm4(uint32_t& r0, uint32_t& r1,
                                             uint32_t& r2, uint32_t& r3,
                                             uint32_t addr) {
    asm volatile("ldmatrix.sync.aligned.m8n8.x4.shared.b16 {%0,%1,%2,%3}, [%4];"
                 : "=r"(r0), "=r"(r1), "=r"(r2), "=r"(r3) : "r"(addr));
}

static __device__ __forceinline__ void ldsm4t(uint32_t& r0, uint32_t& r1,
                                              uint32_t& r2, uint32_t& r3,
                                              uint32_t addr) {
    asm volatile("ldmatrix.sync.aligned.m8n8.x4.trans.shared.b16 {%0,%1,%2,%3}, [%4];"
                 : "=r"(r0), "=r"(r1), "=r"(r2), "=r"(r3) : "r"(addr));
}

static __device__ __forceinline__ void mma16816(float* c, uint32_t a0, uint32_t a1,
                                                uint32_t a2, uint32_t a3,
                                                uint32_t b0, uint32_t b1) {
    asm volatile(
        "mma.sync.aligned.m16n8k16.row.col.f32.f16.f16.f32 "
        "{%0,%1,%2,%3}, {%4,%5,%6,%7}, {%8,%9}, {%0,%1,%2,%3};"
        : "+f"(c[0]), "+f"(c[1]), "+f"(c[2]), "+f"(c[3])
        : "r"(a0), "r"(a1), "r"(a2), "r"(a3), "r"(b0), "r"(b1));
}

static __device__ __forceinline__ uint32_t pack_h2(float a, float b) {
    __half2 h = __floats2half2_rn(a, b);
    return *(uint32_t*)&h;
}

// rotate (v0,v1) by (cos,sin), round to half2
static __device__ __forceinline__ __half2 rope_h2(float v0, float v1, float2 cs) {
    return __floats2half2_rn(v0 * cs.x - v1 * cs.y, v0 * cs.y + v1 * cs.x);
}

// ---------------------------------------------------------------------------
// Cast fp32 -> fp16.  n % 4 == 0.
// ---------------------------------------------------------------------------
__global__ void cast_kernel(const float* __restrict__ X,
                            __half* __restrict__ H, int n4) {
    int i = blockIdx.x * blockDim.x + threadIdx.x;
    if (i >= n4) return;
    float4 v = ((const float4*)X)[i];
    __half2* Hp = (__half2*)H;
    Hp[2 * i]     = __floats2half2_rn(v.x, v.y);
    Hp[2 * i + 1] = __floats2half2_rn(v.z, v.w);
}

// ---------------------------------------------------------------------------
// GEMM geometry: 128x128 CTA tile, BK=32, 8 warps (2x4), warp 64x32,
// 3-stage cp.async, 2 CTAs/SM.
// ---------------------------------------------------------------------------
#define GSTAGES 3
#define GBK     32
#define RS_B    80
#define GTILE_B (128 * RS_B)
#define GSTAGE_B (2 * GTILE_B)
#define GSMEM_BYTES (GSTAGES * GSTAGE_B)   // 61440

static __device__ __forceinline__ void tile_cp(uint32_t sbase,
        const __half* __restrict__ src, int r0, int kc, int K, int tid) {
#pragma unroll
    for (int i = 0; i < 2; i++) {
        int ch  = tid + i * 256;
        int r   = ch >> 2;
        int c16 = ch & 3;
        uint32_t dst = sbase + (uint32_t)(r * RS_B + c16 * 16);
        const void* g = src + (size_t)(r0 + r) * K + kc + c16 * 8;
        asm volatile("cp.async.cg.shared.global [%0], [%1], 16;"
                     :: "r"(dst), "l"(g) : "memory");
    }
}

// ---------------------------------------------------------------------------
// Fused QKV projection GEMM (single-pass fp16, RoPE fused for Q/K blocks).
// Grid x: 0..31 -> Q cols, 32..39 -> K cols, 40..47 -> V cols.
// ---------------------------------------------------------------------------
__global__ __launch_bounds__(256, 2)
void gemm_qkv(const __half* __restrict__ A,
              const __half* __restrict__ Wq, const __half* __restrict__ Wk,
              const __half* __restrict__ Wv, const float* __restrict__ fc,
              __half* __restrict__ Qo, __half* __restrict__ Ko,
              __half* __restrict__ Vo, int M, int K) {
    extern __shared__ __align__(16) char smraw[];
    const uint32_t sb  = smem_u32(smraw);
    const int tid  = threadIdx.x;
    const int wid  = tid >> 5;
    const int lane = tid & 31;
    const int wm   = wid >> 2;
    const int wn   = wid & 3;
    const int bm = blockIdx.y * 128;
    const int bnb = blockIdx.x;

    // Select weight slab / destination / rope flag
    const __half* B;
    __half* C;
    int Nout, colbase;
    bool do_rope;
    if (bnb < 32)      { B = Wq + (size_t)bnb * 128 * K;        C = Qo; Nout = 4096; colbase = bnb * 128;        do_rope = true;  }
    else if (bnb < 40) { B = Wk + (size_t)(bnb - 32) * 128 * K; C = Ko; Nout = 1024; colbase = (bnb - 32) * 128; do_rope = true;  }
    else               { B = Wv + (size_t)(bnb - 40) * 128 * K; C = Vo; Nout = 1024; colbase = (bnb - 40) * 128; do_rope = false; }

    const int a_row = wm * 64 + (lane & 15);
    const int a_colB = ((lane >> 4) * 8) * 2;
    const int b_row = wn * 32 + (lane & 7) + ((lane >> 4) * 8);
    const int b_colB = (((lane >> 3) & 1) * 8) * 2;
    const uint32_t a_off = (uint32_t)(a_row * RS_B + a_colB);
    const uint32_t b_off = (uint32_t)(b_row * RS_B + b_colB);

    float acc[4][4][4];
#pragma unroll
    for (int i = 0; i < 4; i++)
#pragma unroll
        for (int j = 0; j < 4; j++)
#pragma unroll
            for (int k = 0; k < 4; k++) acc[i][j][k] = 0.f;

    const int NC = K / GBK;

#pragma unroll
    for (int i = 0; i < GSTAGES; i++) {
        const uint32_t stg = sb + i * GSTAGE_B;
        tile_cp(stg,           A, bm, i * GBK, K, tid);
        tile_cp(stg + GTILE_B, B, 0,  i * GBK, K, tid);
        asm volatile("cp.async.commit_group;" ::: "memory");
    }

    int s = 0;
    for (int c = 0; c < NC; c++) {
        asm volatile("cp.async.wait_group %0;" :: "n"(GSTAGES - 1) : "memory");
        __syncthreads();

        const uint32_t stg = sb + s * GSTAGE_B;
        const uint32_t Bt  = stg + GTILE_B;
#pragma unroll
        for (int k16 = 0; k16 < 2; k16++) {
            const uint32_t kB = (uint32_t)(k16 * 16 * 2);
            uint32_t a[4][4];
#pragma unroll
            for (int mb = 0; mb < 4; mb++)
                ldsm4(a[mb][0], a[mb][1], a[mb][2], a[mb][3],
                      stg + a_off + mb * (16 * RS_B) + kB);
            uint32_t b[8];
            ldsm4(b[0], b[1], b[2], b[3], Bt + b_off + kB);
            ldsm4(b[4], b[5], b[6], b[7], Bt + b_off + 16 * RS_B + kB);
#pragma unroll
            for (int mb = 0; mb < 4; mb++)
#pragma unroll
                for (int nb = 0; nb < 4; nb++)
                    mma16816(acc[mb][nb], a[mb][0], a[mb][1], a[mb][2], a[mb][3],
                             b[2 * nb], b[2 * nb + 1]);
        }
        __syncthreads();

        const int cn = c + GSTAGES;
        if (cn < NC) {
            const uint32_t stg2 = sb + s * GSTAGE_B;
            tile_cp(stg2,           A, bm, cn * GBK, K, tid);
            tile_cp(stg2 + GTILE_B, B, 0,  cn * GBK, K, tid);
        }
        asm volatile("cp.async.commit_group;" ::: "memory");

        if (++s == GSTAGES) s = 0;
    }

    const int tr = lane >> 2;
    const int tc = (lane & 3) * 2;
#pragma unroll
    for (int mb = 0; mb < 4; mb++) {
        const int row0 = bm + wm * 64 + mb * 16 + tr;
        const int row1 = row0 + 8;
#pragma unroll
        for (int nb = 0; nb < 4; nb++) {
            const int col = colbase + wn * 32 + nb * 8 + tc;
            if (do_rope) {
                const int d = col & (HD - 1);
                float2 cs0 = *(const float2*)(fc + (size_t)row0 * HD + d);
                float2 cs1 = *(const float2*)(fc + (size_t)row1 * HD + d);
                *(__half2*)(C + (size_t)row0 * Nout + col) =
                    rope_h2(acc[mb][nb][0], acc[mb][nb][1], cs0);
                *(__half2*)(C + (size_t)row1 * Nout + col) =
                    rope_h2(acc[mb][nb][2], acc[mb][nb][3], cs1);
            } else {
                *(__half2*)(C + (size_t)row0 * Nout + col) =
                    __floats2half2_rn(acc[mb][nb][0], acc[mb][nb][1]);
                *(__half2*)(C + (size_t)row1 * Nout + col) =
                    __floats2half2_rn(acc[mb][nb][2], acc[mb][nb][3]);
            }
        }
    }
}

// ---------------------------------------------------------------------------
// 1-pass GEMM, fp32 out (output projection): C = A @ B^T
// ---------------------------------------------------------------------------
__global__ __launch_bounds__(256, 2)
void gemm_f16_f32(const __half* __restrict__ A, const __half* __restrict__ B,
                  float* __restrict__ C, int M, int N, int K) {
    extern __shared__ __align__(16) char smraw[];
    const uint32_t sb  = smem_u32(smraw);
    const int tid  = threadIdx.x;
    const int wid  = tid >> 5;
    const int lane = tid & 31;
    const int wm   = wid >> 2;
    const int wn   = wid & 3;
    const int bm = blockIdx.y * 128;
    const int bn = blockIdx.x * 128;

    const int a_row = wm * 64 + (lane & 15);
    const int a_colB = ((lane >> 4) * 8) * 2;
    const int b_row = wn * 32 + (lane & 7) + ((lane >> 4) * 8);
    const int b_colB = (((lane >> 3) & 1) * 8) * 2;
    const uint32_t a_off = (uint32_t)(a_row * RS_B + a_colB);
    const uint32_t b_off = (uint32_t)(b_row * RS_B + b_colB);

    float acc[4][4][4];
#pragma unroll
    for (int i = 0; i < 4; i++)
#pragma unroll
        for (int j = 0; j < 4; j++)
#pragma unroll
            for (int k = 0; k < 4; k++) acc[i][j][k] = 0.f;

    const int NC = K / GBK;

#pragma unroll
    for (int i = 0; i < GSTAGES; i++) {
        const uint32_t stg = sb + i * GSTAGE_B;
        tile_cp(stg,           A, bm, i * GBK, K, tid);
        tile_cp(stg + GTILE_B, B, bn, i * GBK, K, tid);
        asm volatile("cp.async.commit_group;" ::: "memory");
    }

    int s = 0;
    for (int c = 0; c < NC; c++) {
        asm volatile("cp.async.wait_group %0;" :: "n"(GSTAGES - 1) : "memory");
        __syncthreads();

        const uint32_t stg = sb + s * GSTAGE_B;
        const uint32_t Bt  = stg + GTILE_B;
#pragma unroll
        for (int k16 = 0; k16 < 2; k16++) {
            const uint32_t kB = (uint32_t)(k16 * 16 * 2);
            uint32_t a[4][4];
#pragma unroll
            for (int mb = 0; mb < 4; mb++)
                ldsm4(a[mb][0], a[mb][1], a[mb][2], a[mb][3],
                      stg + a_off + mb * (16 * RS_B) + kB);
            uint32_t b[8];
            ldsm4(b[0], b[1], b[2], b[3], Bt + b_off + kB);
            ldsm4(b[4], b[5], b[6], b[7], Bt + b_off + 16 * RS_B + kB);
#pragma unroll
            for (int mb = 0; mb < 4; mb++)
#pragma unroll
                for (int nb = 0; nb < 4; nb++)
                    mma16816(acc[mb][nb], a[mb][0], a[mb][1], a[mb][2], a[mb][3],
                             b[2 * nb], b[2 * nb + 1]);
        }
        __syncthreads();

        const int cn = c + GSTAGES;
        if (cn < NC) {
            const uint32_t stg2 = sb + s * GSTAGE_B;
            tile_cp(stg2,           A, bm, cn * GBK, K, tid);
            tile_cp(stg2 + GTILE_B, B, bn, cn * GBK, K, tid);
        }
        asm volatile("cp.async.commit_group;" ::: "memory");

        if (++s == GSTAGES) s = 0;
    }

    const int tr = lane >> 2;
    const int tc = (lane & 3) * 2;
#pragma unroll
    for (int mb = 0; mb < 4; mb++) {
        const int row = bm + wm * 64 + mb * 16 + tr;
#pragma unroll
        for (int nb = 0; nb < 4; nb++) {
            const int col = bn + wn * 32 + nb * 8 + tc;
            float* c0 = C + (size_t)row * N + col;
            *(float2*)c0 = make_float2(acc[mb][nb][0], acc[mb][nb][1]);
            float* c1 = C + (size_t)(row + 8) * N + col;
            *(float2*)c1 = make_float2(acc[mb][nb][2], acc[mb][nb][3]);
        }
    }
}

// ---------------------------------------------------------------------------
// HMMA flash attention: 64q x 64k tiles, 4 warps, online softmax in regs.
// Q/K/V fp16, O written fp16 at [s][h*128+d].
// ---------------------------------------------------------------------------
#define AKS 136                               // half stride (272 B) per row
#define ATTN_SMEM_BYTES (5 * 64 * AKS * 2 + 256)

static __device__ __forceinline__ void attn_load_kv(
        uint32_t uK, uint32_t uV,
        const __half* __restrict__ Kh, const __half* __restrict__ Vh,
        int k0, int kvh, int tid) {
#pragma unroll
    for (int i = 0; i < 8; i++) {
        int ch = tid + i * 128;
        int r  = ch >> 4;
        int c  = ch & 15;
        size_t goff = (size_t)(k0 + r) * (HKV * HD) + kvh * HD + c * 8;
        uint32_t soff = (uint32_t)(r * AKS + c * 8) * 2;
        asm volatile("cp.async.cg.shared.global [%0], [%1], 16;"
                     :: "r"(uK + soff), "l"((const void*)(Kh + goff)) : "memory");
        asm volatile("cp.async.cg.shared.global [%0], [%1], 16;"
                     :: "r"(uV + soff), "l"((const void*)(Vh + goff)) : "memory");
    }
}

__global__ __launch_bounds__(128, 2)
void attn_hmma(const __half* __restrict__ Qh, const __half* __restrict__ Kh,
               const __half* __restrict__ Vh, const int* __restrict__ seqlens,
               int nseq, __half* __restrict__ Oh, int S) {
    extern __shared__ __align__(16) char smraw[];
    const uint32_t sb  = smem_u32(smraw);
    const uint32_t uQ  = sb;
    const uint32_t uK0 = sb + 1 * (64 * AKS * 2);
    const uint32_t uV0 = sb + 3 * (64 * AKS * 2);
    int* seg_s = (int*)(smraw + 5 * (64 * AKS * 2));

    const int tid  = threadIdx.x;
    const int wid  = tid >> 5;
    const int lane = tid & 31;
    const int h    = blockIdx.y;
    const int kvh  = h / REP;
    const int qb   = gridDim.x - 1 - (int)blockIdx.x;   // heavy blocks first
    const int q0   = qb * 64;

    int kt_lo;
    {
        int cum = 0, ss = 0;
        for (int i = 0; i < nseq; i++) {
            int nc = cum + seqlens[i];
            if (q0 < nc) { ss = cum; break; }
            cum = nc;
        }
        kt_lo = ss >> 6;
    }

    // Q tile -> smem
#pragma unroll
    for (int i = 0; i < 8; i++) {
        int ch = tid + i * 128;
        int r  = ch >> 4;
        int c  = ch & 15;
        uint32_t dst = uQ + (uint32_t)(r * AKS + c * 8) * 2;
        const void* g = Qh + (size_t)(q0 + r) * (HQ * HD) + h * HD + c * 8;
        asm volatile("cp.async.cg.shared.global [%0], [%1], 16;"
                     :: "r"(dst), "l"(g) : "memory");
    }
    asm volatile("cp.async.commit_group;" ::: "memory");

    attn_load_kv(uK0, uV0, Kh, Vh, kt_lo * 64, kvh, tid);
    asm volatile("cp.async.commit_group;" ::: "memory");

    if (tid < 64) {
        int qg = q0 + tid;
        int cum = 0, ss = 0;
        for (int i = 0; i < nseq; i++) {
            int nc = cum + seqlens[i];
            if (qg < nc) { ss = cum; break; }
            cum = nc;
        }
        seg_s[tid] = ss;
    }

    asm volatile("cp.async.wait_group 0;" ::: "memory");
    __syncthreads();

    uint32_t qf[8][4];
    {
        const uint32_t a_off =
            (uint32_t)((wid * 16 + (lane & 15)) * AKS + (lane >> 4) * 8) * 2;
#pragma unroll
        for (int kb = 0; kb < 8; kb++)
            ldsm4(qf[kb][0], qf[kb][1], qf[kb][2], qf[kb][3],
                  uQ + a_off + kb * 32);
    }

    const uint32_t bk_off =
        (uint32_t)(((lane & 7) + ((lane >> 4) * 8)) * AKS + ((lane >> 3) & 1) * 8) * 2;
    const uint32_t bv_off =
        (uint32_t)((lane & 15) * AKS + (lane >> 4) * 8) * 2;

    const int tr  = lane >> 2;
    const int r0l = wid * 16 + tr;
    const int r0g = q0 + r0l;
    const int r1g = r0g + 8;
    const int ss0 = seg_s[r0l];
    const int ss1 = seg_s[r0l + 8];

    float oa[16][4];
#pragma unroll
    for (int i = 0; i < 16; i++)
#pragma unroll
        for (int j = 0; j < 4; j++) oa[i][j] = 0.f;
    float m0 = -1e30f, m1 = -1e30f, l0 = 0.f, l1 = 0.f;

    const int nt = qb - kt_lo + 1;
    int buf = 0;
    for (int t = 0; t < nt; t++) {
        const int k0 = (kt_lo + t) * 64;
        if (t + 1 < nt)
            attn_load_kv(uK0 + (buf ^ 1) * (64 * AKS * 2),
                         uV0 + (buf ^ 1) * (64 * AKS * 2),
                         Kh, Vh, (kt_lo + t + 1) * 64, kvh, tid);
        asm volatile("cp.async.commit_group;" ::: "memory");
        if (t > 0) {
            if (t + 1 < nt)
                asm volatile("cp.async.wait_group 1;" ::: "memory");
            else
                asm volatile("cp.async.wait_group 0;" ::: "memory");
            __syncthreads();
        }

        const uint32_t uKb = uK0 + buf * (64 * AKS * 2);
        const uint32_t uVb = uV0 + buf * (64 * AKS * 2);

        float sc[8][4];
#pragma unroll
        for (int i = 0; i < 8; i++)
#pragma unroll
            for (int j = 0; j < 4; j++) sc[i][j] = 0.f;
#pragma unroll
        for (int kb = 0; kb < 8; kb++) {
#pragma unroll
            for (int nbp = 0; nbp < 4; nbp++) {
                uint32_t b0, b1, b2, b3;
                ldsm4(b0, b1, b2, b3,
                      uKb + bk_off + nbp * (16 * AKS * 2) + kb * 32);
                mma16816(sc[2 * nbp],     qf[kb][0], qf[kb][1], qf[kb][2], qf[kb][3], b0, b1);
                mma16816(sc[2 * nbp + 1], qf[kb][0], qf[kb][1], qf[kb][2], qf[kb][3], b2, b3);
            }
        }

        float mx0 = -1e30f, mx1 = -1e30f;
#pragma unroll
        for (int nb = 0; nb < 8; nb++) {
            int kbase = k0 + nb * 8 + (lane & 3) * 2;
#pragma unroll
            for (int c = 0; c < 2; c++) {
                int kg = kbase + c;
                float v0 = sc[nb][c] * ATT_SCALE;
                float v1 = sc[nb][2 + c] * ATT_SCALE;
                v0 = (kg <= r0g && kg >= ss0) ? v0 : -1e30f;
                v1 = (kg <= r1g && kg >= ss1) ? v1 : -1e30f;
                sc[nb][c] = v0; sc[nb][2 + c] = v1;
                mx0 = fmaxf(mx0, v0); mx1 = fmaxf(mx1, v1);
            }
        }
        mx0 = fmaxf(mx0, __shfl_xor_sync(0xffffffffu, mx0, 1));
        mx0 = fmaxf(mx0, __shfl_xor_sync(0xffffffffu, mx0, 2));
        mx1 = fmaxf(mx1, __shfl_xor_sync(0xffffffffu, mx1, 1));
        mx1 = fmaxf(mx1, __shfl_xor_sync(0xffffffffu, mx1, 2));

        const float m0n = fmaxf(m0, mx0);
        const float m1n = fmaxf(m1, mx1);
        const float al0 = __expf(m0 - m0n);
        const float al1 = __expf(m1 - m1n);

        float s0 = 0.f, s1 = 0.f;
#pragma unroll
        for (int nb = 0; nb < 8; nb++) {
#pragma unroll
            for (int c = 0; c < 2; c++) {
                float p0 = __expf(sc[nb][c]     - m0n);
                float p1 = __expf(sc[nb][2 + c] - m1n);
                sc[nb][c] = p0; sc[nb][2 + c] = p1;
                s0 += p0; s1 += p1;
            }
        }
        s0 += __shfl_xor_sync(0xffffffffu, s0, 1);
        s0 += __shfl_xor_sync(0xffffffffu, s0, 2);
        s1 += __shfl_xor_sync(0xffffffffu, s1, 1);
        s1 += __shfl_xor_sync(0xffffffffu, s1, 2);
        l0 = l0 * al0 + s0;
        l1 = l1 * al1 + s1;
        m0 = m0n; m1 = m1n;

#pragma unroll
        for (int nb = 0; nb < 16; nb++) {
            oa[nb][0] *= al0; oa[nb][1] *= al0;
            oa[nb][2] *= al1; oa[nb][3] *= al1;
        }

#pragma unroll
        for (int kb2 = 0; kb2 < 4; kb2++) {
            uint32_t pf0 = pack_h2(sc[2 * kb2][0],     sc[2 * kb2][1]);
            uint32_t pf1 = pack_h2(sc[2 * kb2][2],     sc[2 * kb2][3]);
            uint32_t pf2 = pack_h2(sc[2 * kb2 + 1][0], sc[2 * kb2 + 1][1]);
            uint32_t pf3 = pack_h2(sc[2 * kb2 + 1][2], sc[2 * kb2 + 1][3]);
#pragma unroll
            for (int nbp = 0; nbp < 8; nbp++) {
                uint32_t b0, b1, b2, b3;
                ldsm4t(b0, b1, b2, b3,
                       uVb + bv_off + kb2 * (16 * AKS * 2) + nbp * 32);
                mma16816(oa[2 * nbp],     pf0, pf1, pf2, pf3, b0, b1);
                mma16816(oa[2 * nbp + 1], pf0, pf1, pf2, pf3, b2, b3);
            }
        }

        __syncthreads();
        buf ^= 1;
    }

    const float inv0 = 1.f / l0;
    const float inv1 = 1.f / l1;
    __half* orow0 = Oh + (size_t)r0g * (HQ * HD) + h * HD;
    __half* orow1 = Oh + (size_t)r1g * (HQ * HD) + h * HD;
#pragma unroll
    for (int nb = 0; nb < 16; nb++) {
        int col = nb * 8 + (lane & 3) * 2;
        *(__half2*)(orow0 + col) = __floats2half2_rn(oa[nb][0] * inv0, oa[nb][1] * inv0);
        *(__half2*)(orow1 + col) = __floats2half2_rn(oa[nb][2] * inv1, oa[nb][3] * inv1);
    }
}

// ---------------------------------------------------------------------------
// Launch
// Inputs: 0:x[S,4096] 1:freqs_cis[S,64,2] 2:seqlens[int32 x nseq]
//         3:wq[4096,4096] 4:wk[1024,4096] 5:wv[1024,4096] 6:wo[4096,4096]
// Output: float32 [S, 4096]
// ---------------------------------------------------------------------------
extern "C" void kernel_launch(void* const* d_in, const int* in_sizes, int n_in,
                              void* d_out, int out_size) {
    const float* x  = (const float*)d_in[0];
    const float* fc = (const float*)d_in[1];
    const int*   sl = (const int*)d_in[2];
    const float* wq = (const float*)d_in[3];
    const float* wk = (const float*)d_in[4];
    const float* wv = (const float*)d_in[5];
    const float* wo = (const float*)d_in[6];
    float* out = (float*)d_out;

    const int S    = in_sizes[0] / DIMK;   // 2048
    const int nseq = in_sizes[2];

    __half *xh, *oh, *qh, *kh, *vh, *wqh, *wkh, *wvh, *woh;
    cudaGetSymbolAddress((void**)&xh,  g_xh);
    cudaGetSymbolAddress((void**)&oh,  g_oh);
    cudaGetSymbolAddress((void**)&qh,  g_qh);
    cudaGetSymbolAddress((void**)&kh,  g_kh);
    cudaGetSymbolAddress((void**)&vh,  g_vh);
    cudaGetSymbolAddress((void**)&wqh, g_wqh);
    cudaGetSymbolAddress((void**)&wkh, g_wkh);
    cudaGetSymbolAddress((void**)&wvh, g_wvh);
    cudaGetSymbolAddress((void**)&woh, g_woh);

    cudaFuncSetAttribute(gemm_qkv, cudaFuncAttributeMaxDynamicSharedMemorySize,
                         GSMEM_BYTES);
    cudaFuncSetAttribute(gemm_f16_f32, cudaFuncAttributeMaxDynamicSharedMemorySize,
                         GSMEM_BYTES);
    cudaFuncSetAttribute(attn_hmma, cudaFuncAttributeMaxDynamicSharedMemorySize,
                         ATTN_SMEM_BYTES);

    // Cast activations + all weights to plain fp16
    {
        int n;
        n = S * DIMK;       cast_kernel<<<(n / 4 + 255) / 256, 256>>>(x, xh, n / 4);
        n = 4096 * 4096;    cast_kernel<<<(n / 4 + 255) / 256, 256>>>(wq, wqh, n / 4);
        n = 1024 * 4096;    cast_kernel<<<(n / 4 + 255) / 256, 256>>>(wk, wkh, n / 4);
        n = 1024 * 4096;    cast_kernel<<<(n / 4 + 255) / 256, 256>>>(wv, wvh, n / 4);
        n = 4096 * 4096;    cast_kernel<<<(n / 4 + 255) / 256, 256>>>(wo, woh, n / 4);
    }

    // Fused QKV projection (RoPE fused for Q/K; fp16 outputs)
    gemm_qkv<<<dim3(48, S / 128), 256, GSMEM_BYTES>>>(
        xh, wqh, wkh, wvh, fc, qh, kh, vh, S, DIMK);

    // Attention (HMMA, fp16 in/out)
    attn_hmma<<<dim3(S / 64, HQ), 128, ATTN_SMEM_BYTES>>>(qh, kh, vh, sl, nseq, oh, S);

    // Output projection (single-pass fp16, fp32 out)
    gemm_f16_f32<<<dim3(4096 / 128, S / 128), 256, GSMEM_BYTES>>>(
        oh, woh, out, S, 4096, DIMK);
}